// round 14
// baseline (speedup 1.0000x reference)
#include <cuda_runtime.h>
#include <cuda_fp16.h>
#include <cstdint>

#define H     128
#define MAXN  50000
#define MAXE  640000
#define PC    256                // g_P columns: [T | C]

#define BK      64
#define S_H     72               // smem row stride (halves); 72/2 % 32 == 4 -> conflict-free frags
#define TILE_H  (128 * S_H)      // halves per smem tile
#define SMEM_BYTES (2 * TILE_H * 2)

// ---- scratch (static device memory) ----
__device__ __align__(16) __half g_Bt[384 * H];    // GEMM1 B^T: [n][k] half
__device__ __align__(16) __half g_Bu[H * H];      // GEMM2 B^T: Wu2^T [n][k] half
__device__ __align__(16) float  g_v[H];           // W_msg weight column
__device__ __align__(16) __half g_A16[MAXN * H];  // fp16 A slab (12.8 MB, L2-resident)
__device__ __align__(16) float  g_P[MAXN * PC];   // per-node [T | C] fp32
__device__ __align__(16) __half g_agg16[MAXN * H];// aggregated (max + T, or 0) fp16
// CSR build
__device__ int   g_cnt[MAXN];
__device__ int   g_ro[MAXN];
__device__ int   g_cur[MAXN];
__device__ int   g_bsum[128];
__device__ int   g_boff[128];
__device__ int   g_es[MAXE];
__device__ float g_ew[MAXE];

__device__ __forceinline__ void mma_f16(float* acc, const uint32_t* a, const uint32_t* b) {
    asm volatile(
        "mma.sync.aligned.m16n8k16.row.col.f32.f16.f16.f32 "
        "{%0,%1,%2,%3}, {%4,%5,%6,%7}, {%8,%9}, {%0,%1,%2,%3};"
        : "+f"(acc[0]), "+f"(acc[1]), "+f"(acc[2]), "+f"(acc[3])
        : "r"(a[0]), "r"(a[1]), "r"(a[2]), "r"(a[3]), "r"(b[0]), "r"(b[1]));
}
__device__ __forceinline__ uint32_t pack_h2(float x, float y) {
    __half2 h = __floats2half2_rn(x, y);
    return *reinterpret_cast<uint32_t*>(&h);
}

// ---------------------------------------------------------------------------
// Pack weights into half (transposed for col-major B frags).
// ---------------------------------------------------------------------------
__global__ void pack_kernel(const float* __restrict__ Wmsg,
                            const float* __restrict__ Wupd) {
    int idx = blockIdx.x * blockDim.x + threadIdx.x;
    if (idx < H) g_v[idx] = Wmsg[256 * H + idx];
    if (idx < 384 * H) {
        int n = idx / H, k = idx % H;
        float val;
        if (n < H)            val = Wmsg[k * H + n];
        else if (n < 2 * H)   val = Wmsg[(H + k) * H + (n - H)];
        else                  val = Wupd[k * H + (n - 2 * H)];
        g_Bt[idx] = __float2half_rn(val);
    } else if (idx < 384 * H + H * H) {
        int j = idx - 384 * H;
        int n = j / H, k = j % H;
        g_Bu[j] = __float2half_rn(Wupd[(H + k) * H + n]);
    }
}

// ---------------------------------------------------------------------------
// CSR build: zero -> histogram -> scan(3 stages) -> scatter
// ---------------------------------------------------------------------------
__global__ void zero_cnt_kernel(int n) {
    int i = blockIdx.x * blockDim.x + threadIdx.x;
    if (i < n) g_cnt[i] = 0;
}

__global__ void hist_kernel(const int* __restrict__ dst, int E) {
    int i = blockIdx.x * blockDim.x + threadIdx.x;
    if (i < E) atomicAdd(&g_cnt[dst[i]], 1);
}

__global__ void scan1_kernel(int n) {
    __shared__ int s[512];
    int t = threadIdx.x;
    int i = blockIdx.x * 512 + t;
    int v = (i < n) ? g_cnt[i] : 0;
    s[t] = v;
    __syncthreads();
    #pragma unroll
    for (int off = 1; off < 512; off <<= 1) {
        int u = (t >= off) ? s[t - off] : 0;
        __syncthreads();
        s[t] += u;
        __syncthreads();
    }
    if (i < n) g_ro[i] = s[t] - v;            // exclusive within block
    if (t == 511) g_bsum[blockIdx.x] = s[511];
}

__global__ void scan2_kernel(int nb) {
    __shared__ int s[128];
    int t = threadIdx.x;
    int v = (t < nb) ? g_bsum[t] : 0;
    s[t] = v;
    __syncthreads();
    #pragma unroll
    for (int off = 1; off < 128; off <<= 1) {
        int u = (t >= off) ? s[t - off] : 0;
        __syncthreads();
        s[t] += u;
        __syncthreads();
    }
    if (t < nb) g_boff[t] = s[t] - v;         // exclusive block offsets
}

__global__ void scan3_kernel(int n) {
    int i = blockIdx.x * blockDim.x + threadIdx.x;
    if (i < n) {
        int v = g_ro[i] + g_boff[i >> 9];
        g_ro[i] = v;
        g_cur[i] = v;
    }
}

__global__ void scatter_kernel(const int* __restrict__ src,
                               const int* __restrict__ dst,
                               const float* __restrict__ w, int E) {
    int i = blockIdx.x * blockDim.x + threadIdx.x;
    if (i < E) {
        int d = dst[i];
        int p = atomicAdd(&g_cur[d], 1);
        g_es[p] = src[i];
        g_ew[p] = w[i];
    }
}

// ---------------------------------------------------------------------------
// Aggregate: one warp per node (R12 shape); 16-edge batches for deep MLP.
// A gathered from fp16 slab (8 B/lane); math fp32; writes fp16 agg.
// Max is exact/associative -> deterministic.
// ---------------------------------------------------------------------------
__global__ void __launch_bounds__(256)
aggregate_kernel(int n) {
    int node = (blockIdx.x * blockDim.x + threadIdx.x) >> 5;
    int lane = threadIdx.x & 31;
    if (node >= n) return;
    int start = g_ro[node];
    int deg   = g_cnt[node];

    float4 vv = *reinterpret_cast<const float4*>(g_v + lane * 4);
    const float NEGINF = __int_as_float(0xff800000);
    float4 m = make_float4(NEGINF, NEGINF, NEGINF, NEGINF);

    for (int e = 0; e < deg; e += 16) {
        int nb = deg - e; if (nb > 16) nb = 16;
        int s16[16]; float w16[16];
        #pragma unroll
        for (int j = 0; j < 16; j++) {
            int idx = start + e + ((j < nb) ? j : 0);
            s16[j] = __ldg(g_es + idx);
            w16[j] = __ldg(g_ew + idx);
        }
        uint2 a16[16];
        #pragma unroll
        for (int j = 0; j < 16; j++)
            a16[j] = __ldg(reinterpret_cast<const uint2*>(g_A16 + s16[j] * H) + lane);
        #pragma unroll
        for (int j = 0; j < 16; j++) {
            if (j < nb) {
                __half2 h0 = *reinterpret_cast<__half2*>(&a16[j].x);
                __half2 h1 = *reinterpret_cast<__half2*>(&a16[j].y);
                float2 f0 = __half22float2(h0);
                float2 f1 = __half22float2(h1);
                m.x = fmaxf(m.x, fmaf(w16[j], vv.x, f0.x));
                m.y = fmaxf(m.y, fmaf(w16[j], vv.y, f0.y));
                m.z = fmaxf(m.z, fmaf(w16[j], vv.z, f1.x));
                m.w = fmaxf(m.w, fmaf(w16[j], vv.w, f1.y));
            }
        }
    }

    uint2 o;
    if (deg > 0) {
        float4 t4 = *reinterpret_cast<const float4*>(g_P + node * PC + lane * 4);
        o.x = pack_h2(m.x + t4.x, m.y + t4.y);
        o.y = pack_h2(m.z + t4.z, m.w + t4.w);
    } else {
        o.x = 0u; o.y = 0u;
    }
    *reinterpret_cast<uint2*>(g_agg16 + node * H + lane * 4) = o;
}

// ---------------------------------------------------------------------------
// mma compute core (fp16 m16n8k16): 8 warps (2x4), warp tile 64x32, BK=64.
// ---------------------------------------------------------------------------
__device__ __forceinline__ void mma_chunk16(const __half* As, const __half* Bs,
                                            float acc[4][4][4], int wm, int wn, int lane) {
    const int qr = lane >> 2, qk = lane & 3;
    #pragma unroll
    for (int ks = 0; ks < BK / 16; ks++) {
        uint32_t a[4][4], b[4][2];
        #pragma unroll
        for (int mt = 0; mt < 4; mt++) {
            const __half* p = As + (wm * 64 + mt * 16 + qr) * S_H + ks * 16 + qk * 2;
            a[mt][0] = *reinterpret_cast<const uint32_t*>(p);
            a[mt][1] = *reinterpret_cast<const uint32_t*>(p + 8 * S_H);
            a[mt][2] = *reinterpret_cast<const uint32_t*>(p + 8);
            a[mt][3] = *reinterpret_cast<const uint32_t*>(p + 8 * S_H + 8);
        }
        #pragma unroll
        for (int nt = 0; nt < 4; nt++) {
            const __half* p = Bs + (wn * 32 + nt * 8 + qr) * S_H + ks * 16 + qk * 2;
            b[nt][0] = *reinterpret_cast<const uint32_t*>(p);
            b[nt][1] = *reinterpret_cast<const uint32_t*>(p + 8);
        }
        #pragma unroll
        for (int mt = 0; mt < 4; mt++)
            #pragma unroll
            for (int nt = 0; nt < 4; nt++)
                mma_f16(acc[mt][nt], a[mt], b[nt]);
    }
}

// ---------------------------------------------------------------------------
// GEMM1 (fp16 mma): tile t=blockIdx.y of z @ Wcat.
// t=0 -> A (fp16 slab), t=1 -> T (+b_msg), t=2 -> C
// ---------------------------------------------------------------------------
__global__ void __launch_bounds__(256, 2)
gemm1_mma(const float* __restrict__ z, const float* __restrict__ bmsg, int M) {
    extern __shared__ __half smh[];
    __half* As = smh;
    __half* Bs = smh + TILE_H;
    const int tid = threadIdx.x, wid = tid >> 5, lane = tid & 31;
    const int wm = wid >> 2, wn = wid & 3;
    const int bm = blockIdx.x * 128;
    const int t  = blockIdx.y;
    const int bn = t * 128;
    const int lrow = tid >> 1, lhalf = tid & 1;
    float acc[4][4][4] = {};

    for (int c = 0; c < 2; c++) {
        int k0 = c * BK;
        #pragma unroll
        for (int i = 0; i < 8; i++) {
            int col = lhalf * 4 + i * 8;
            float4 av = make_float4(0.f, 0.f, 0.f, 0.f);
            if (bm + lrow < M)
                av = *reinterpret_cast<const float4*>(z + (bm + lrow) * H + k0 + col);
            uint2 ah; ah.x = pack_h2(av.x, av.y); ah.y = pack_h2(av.z, av.w);
            *reinterpret_cast<uint2*>(As + lrow * S_H + col) = ah;
            uint2 bh = *reinterpret_cast<const uint2*>(g_Bt + (bn + lrow) * H + k0 + col);
            *reinterpret_cast<uint2*>(Bs + lrow * S_H + col) = bh;
        }
        __syncthreads();
        mma_chunk16(As, Bs, acc, wm, wn, lane);
        __syncthreads();
    }

    const int qr = lane >> 2, qk = lane & 3;
    #pragma unroll
    for (int mt = 0; mt < 4; mt++) {
        #pragma unroll
        for (int nt = 0; nt < 4; nt++) {
            int lc = wn * 32 + nt * 8 + qk * 2;      // local col within 128-tile
            int r0 = bm + wm * 64 + mt * 16 + qr;
            int r1 = r0 + 8;
            if (t == 0) {
                if (r0 < M)
                    *reinterpret_cast<uint32_t*>(g_A16 + r0 * H + lc) =
                        pack_h2(acc[mt][nt][0], acc[mt][nt][1]);
                if (r1 < M)
                    *reinterpret_cast<uint32_t*>(g_A16 + r1 * H + lc) =
                        pack_h2(acc[mt][nt][2], acc[mt][nt][3]);
            } else {
                float bx = 0.f, by = 0.f;
                int off = (t == 1) ? lc : (128 + lc);
                if (t == 1) { bx = bmsg[lc]; by = bmsg[lc + 1]; }
                if (r0 < M) {
                    float2 v = make_float2(acc[mt][nt][0] + bx, acc[mt][nt][1] + by);
                    *reinterpret_cast<float2*>(g_P + r0 * PC + off) = v;
                }
                if (r1 < M) {
                    float2 v = make_float2(acc[mt][nt][2] + bx, acc[mt][nt][3] + by);
                    *reinterpret_cast<float2*>(g_P + r1 * PC + off) = v;
                }
            }
        }
    }
}

// ---------------------------------------------------------------------------
// GEMM2 (fp16 mma): out = agg @ Wu2 + C + b_upd; A = g_agg16 (pure copy).
// ---------------------------------------------------------------------------
__global__ void __launch_bounds__(256, 2)
gemm2_mma(const float* __restrict__ bupd, float* __restrict__ out, int M) {
    extern __shared__ __half smh[];
    __half* As = smh;
    __half* Bs = smh + TILE_H;
    const int tid = threadIdx.x, wid = tid >> 5, lane = tid & 31;
    const int wm = wid >> 2, wn = wid & 3;
    const int bm = blockIdx.x * 128;
    const int lrow = tid >> 1, lhalf = tid & 1;
    float acc[4][4][4] = {};

    for (int c = 0; c < 2; c++) {
        int k0 = c * BK;
        #pragma unroll
        for (int i = 0; i < 8; i++) {
            int col = lhalf * 4 + i * 8;
            uint2 ah = make_uint2(0u, 0u);
            if (bm + lrow < M)
                ah = *reinterpret_cast<const uint2*>(g_agg16 + (bm + lrow) * H + k0 + col);
            *reinterpret_cast<uint2*>(As + lrow * S_H + col) = ah;
            uint2 bh = *reinterpret_cast<const uint2*>(g_Bu + lrow * H + k0 + col);
            *reinterpret_cast<uint2*>(Bs + lrow * S_H + col) = bh;
        }
        __syncthreads();
        mma_chunk16(As, Bs, acc, wm, wn, lane);
        __syncthreads();
    }

    const int qr = lane >> 2, qk = lane & 3;
    #pragma unroll
    for (int mt = 0; mt < 4; mt++) {
        #pragma unroll
        for (int nt = 0; nt < 4; nt++) {
            int col = wn * 32 + nt * 8 + qk * 2;
            float bx = bupd[col], by = bupd[col + 1];
            int r0 = bm + wm * 64 + mt * 16 + qr;
            if (r0 < M) {
                float2 c2 = *reinterpret_cast<const float2*>(g_P + r0 * PC + 128 + col);
                float2 v = make_float2(acc[mt][nt][0] + c2.x + bx,
                                       acc[mt][nt][1] + c2.y + by);
                *reinterpret_cast<float2*>(out + r0 * H + col) = v;
            }
            int r1 = r0 + 8;
            if (r1 < M) {
                float2 c2 = *reinterpret_cast<const float2*>(g_P + r1 * PC + 128 + col);
                float2 v = make_float2(acc[mt][nt][2] + c2.x + bx,
                                       acc[mt][nt][3] + c2.y + by);
                *reinterpret_cast<float2*>(out + r1 * H + col) = v;
            }
        }
    }
}

// ---------------------------------------------------------------------------
extern "C" void kernel_launch(void* const* d_in, const int* in_sizes, int n_in,
                              void* d_out, int out_size) {
    const float* z    = (const float*)d_in[0];
    const int*   src  = (const int*)  d_in[1];
    const int*   dst  = (const int*)  d_in[2];
    const float* w    = (const float*)d_in[3];
    const float* Wmsg = (const float*)d_in[4];
    const float* bmsg = (const float*)d_in[5];
    const float* Wupd = (const float*)d_in[6];
    const float* bupd = (const float*)d_in[7];
    float* out = (float*)d_out;

    int n = in_sizes[0] / H;     // 50000
    int E = in_sizes[1];         // 640000

    static cudaStream_t s2 = nullptr;
    static cudaEvent_t evStart = nullptr, evCsr = nullptr;
    static bool init_done = false;
    if (!init_done) {            // first call is the uncaptured correctness run
        cudaFuncSetAttribute(gemm1_mma, cudaFuncAttributeMaxDynamicSharedMemorySize, SMEM_BYTES);
        cudaFuncSetAttribute(gemm2_mma, cudaFuncAttributeMaxDynamicSharedMemorySize, SMEM_BYTES);
        cudaStreamCreateWithFlags(&s2, cudaStreamNonBlocking);
        cudaEventCreateWithFlags(&evStart, cudaEventDisableTiming);
        cudaEventCreateWithFlags(&evCsr, cudaEventDisableTiming);
        init_done = true;
    }

    int nb_scan = (n + 511) / 512;
    int nbk = (n + 127) / 128;

    // fork: CSR build on s2, weights+GEMM1 on main stream
    cudaEventRecord(evStart, 0);
    cudaStreamWaitEvent(s2, evStart, 0);

    zero_cnt_kernel<<<(n + 255) / 256, 256, 0, s2>>>(n);
    hist_kernel<<<(E + 255) / 256, 256, 0, s2>>>(dst, E);
    scan1_kernel<<<nb_scan, 512, 0, s2>>>(n);
    scan2_kernel<<<1, 128, 0, s2>>>(nb_scan);
    scan3_kernel<<<(n + 255) / 256, 256, 0, s2>>>(n);
    scatter_kernel<<<(E + 255) / 256, 256, 0, s2>>>(src, dst, w, E);
    cudaEventRecord(evCsr, s2);

    pack_kernel<<<256, 256>>>(Wmsg, Wupd);
    gemm1_mma<<<dim3(nbk, 3), 256, SMEM_BYTES>>>(z, bmsg, n);

    // join: aggregate needs both gemm1 (A16, T) and scatter (CSR)
    cudaStreamWaitEvent(0, evCsr, 0);
    aggregate_kernel<<<(n * 32 + 255) / 256, 256>>>(n);
    gemm2_mma<<<nbk, 256, SMEM_BYTES>>>(bupd, out, n);
}

// round 15
// speedup vs baseline: 1.2840x; 1.2840x over previous
#include <cuda_runtime.h>
#include <cuda_fp16.h>
#include <cstdint>

#define H     128
#define MAXN  50000
#define MAXE  640000
#define PC    256                // g_P columns: [T | C]

#define BK      64
#define S_H     72               // smem row stride (halves); 72/2 % 32 == 4 -> conflict-free frags
#define TILE_H  (128 * S_H)      // halves per smem tile
#define SMEM_BYTES (2 * TILE_H * 2)

// ---- scratch (static device memory) ----
__device__ __align__(16) __half g_Bt[384 * H];    // GEMM1 B^T: [n][k] half
__device__ __align__(16) __half g_Bu[H * H];      // GEMM2 B^T: Wu2^T [n][k] half
__device__ __align__(16) float  g_v[H];           // W_msg weight column
__device__ __align__(16) __half g_A16[MAXN * H];  // fp16 A slab (12.8 MB, L2-resident)
__device__ __align__(16) float  g_P[MAXN * PC];   // per-node [T | C] fp32
__device__ __align__(16) __half g_agg16[MAXN * H];// aggregated (max + T, or 0) fp16
// CSR build
__device__ int   g_cnt[MAXN];
__device__ int   g_ro[MAXN];
__device__ int   g_cur[MAXN];
__device__ int   g_bsum[128];
__device__ int   g_boff[128];
__device__ __align__(8) int2 g_esw[MAXE];         // packed (src, weight-bits)

__device__ __forceinline__ void mma_f16(float* acc, const uint32_t* a, const uint32_t* b) {
    asm volatile(
        "mma.sync.aligned.m16n8k16.row.col.f32.f16.f16.f32 "
        "{%0,%1,%2,%3}, {%4,%5,%6,%7}, {%8,%9}, {%0,%1,%2,%3};"
        : "+f"(acc[0]), "+f"(acc[1]), "+f"(acc[2]), "+f"(acc[3])
        : "r"(a[0]), "r"(a[1]), "r"(a[2]), "r"(a[3]), "r"(b[0]), "r"(b[1]));
}
__device__ __forceinline__ uint32_t pack_h2(float x, float y) {
    __half2 h = __floats2half2_rn(x, y);
    return *reinterpret_cast<uint32_t*>(&h);
}

// ---------------------------------------------------------------------------
// Pack weights into half (transposed for col-major B frags).
// ---------------------------------------------------------------------------
__global__ void pack_kernel(const float* __restrict__ Wmsg,
                            const float* __restrict__ Wupd) {
    int idx = blockIdx.x * blockDim.x + threadIdx.x;
    if (idx < H) g_v[idx] = Wmsg[256 * H + idx];
    if (idx < 384 * H) {
        int n = idx / H, k = idx % H;
        float val;
        if (n < H)            val = Wmsg[k * H + n];
        else if (n < 2 * H)   val = Wmsg[(H + k) * H + (n - H)];
        else                  val = Wupd[k * H + (n - 2 * H)];
        g_Bt[idx] = __float2half_rn(val);
    } else if (idx < 384 * H + H * H) {
        int j = idx - 384 * H;
        int n = j / H, k = j % H;
        g_Bu[j] = __float2half_rn(Wupd[(H + k) * H + n]);
    }
}

// ---------------------------------------------------------------------------
// CSR build: zero -> histogram -> scan(3 stages) -> scatter
// ---------------------------------------------------------------------------
__global__ void zero_cnt_kernel(int n) {
    int i = blockIdx.x * blockDim.x + threadIdx.x;
    if (i < n) g_cnt[i] = 0;
}

__global__ void hist_kernel(const int* __restrict__ dst, int E) {
    int i = blockIdx.x * blockDim.x + threadIdx.x;
    if (i < E) atomicAdd(&g_cnt[dst[i]], 1);
}

__global__ void scan1_kernel(int n) {
    __shared__ int s[512];
    int t = threadIdx.x;
    int i = blockIdx.x * 512 + t;
    int v = (i < n) ? g_cnt[i] : 0;
    s[t] = v;
    __syncthreads();
    #pragma unroll
    for (int off = 1; off < 512; off <<= 1) {
        int u = (t >= off) ? s[t - off] : 0;
        __syncthreads();
        s[t] += u;
        __syncthreads();
    }
    if (i < n) g_ro[i] = s[t] - v;            // exclusive within block
    if (t == 511) g_bsum[blockIdx.x] = s[511];
}

__global__ void scan2_kernel(int nb) {
    __shared__ int s[128];
    int t = threadIdx.x;
    int v = (t < nb) ? g_bsum[t] : 0;
    s[t] = v;
    __syncthreads();
    #pragma unroll
    for (int off = 1; off < 128; off <<= 1) {
        int u = (t >= off) ? s[t - off] : 0;
        __syncthreads();
        s[t] += u;
        __syncthreads();
    }
    if (t < nb) g_boff[t] = s[t] - v;         // exclusive block offsets
}

__global__ void scan3_kernel(int n) {
    int i = blockIdx.x * blockDim.x + threadIdx.x;
    if (i < n) {
        int v = g_ro[i] + g_boff[i >> 9];
        g_ro[i] = v;
        g_cur[i] = v;
    }
}

__global__ void scatter_kernel(const int* __restrict__ src,
                               const int* __restrict__ dst,
                               const float* __restrict__ w, int E) {
    int i = blockIdx.x * blockDim.x + threadIdx.x;
    if (i < E) {
        int d = dst[i];
        int p = atomicAdd(&g_cur[d], 1);
        g_esw[p] = make_int2(src[i], __float_as_int(w[i]));
    }
}

// ---------------------------------------------------------------------------
// Aggregate: one warp per node (R12 shape); 8-edge batches; packed (src,w)
// stream -> one 8 B load per edge on the index path. Math fp32; writes fp16
// agg. Max is exact/associative -> deterministic.
// ---------------------------------------------------------------------------
__global__ void __launch_bounds__(256)
aggregate_kernel(int n) {
    int node = (blockIdx.x * blockDim.x + threadIdx.x) >> 5;
    int lane = threadIdx.x & 31;
    if (node >= n) return;
    int start = g_ro[node];
    int deg   = g_cnt[node];

    float4 vv = *reinterpret_cast<const float4*>(g_v + lane * 4);
    const float NEGINF = __int_as_float(0xff800000);
    float4 m = make_float4(NEGINF, NEGINF, NEGINF, NEGINF);

    for (int e = 0; e < deg; e += 8) {
        int nb = deg - e; if (nb > 8) nb = 8;
        int2 sw8[8];
        #pragma unroll
        for (int j = 0; j < 8; j++) {
            int idx = start + e + ((j < nb) ? j : 0);
            sw8[j] = __ldg(g_esw + idx);
        }
        uint2 a8[8];
        #pragma unroll
        for (int j = 0; j < 8; j++)
            a8[j] = __ldg(reinterpret_cast<const uint2*>(g_A16 + sw8[j].x * H) + lane);
        #pragma unroll
        for (int j = 0; j < 8; j++) {
            if (j < nb) {
                float wt = __int_as_float(sw8[j].y);
                __half2 h0 = *reinterpret_cast<__half2*>(&a8[j].x);
                __half2 h1 = *reinterpret_cast<__half2*>(&a8[j].y);
                float2 f0 = __half22float2(h0);
                float2 f1 = __half22float2(h1);
                m.x = fmaxf(m.x, fmaf(wt, vv.x, f0.x));
                m.y = fmaxf(m.y, fmaf(wt, vv.y, f0.y));
                m.z = fmaxf(m.z, fmaf(wt, vv.z, f1.x));
                m.w = fmaxf(m.w, fmaf(wt, vv.w, f1.y));
            }
        }
    }

    uint2 o;
    if (deg > 0) {
        float4 t4 = *reinterpret_cast<const float4*>(g_P + node * PC + lane * 4);
        o.x = pack_h2(m.x + t4.x, m.y + t4.y);
        o.y = pack_h2(m.z + t4.z, m.w + t4.w);
    } else {
        o.x = 0u; o.y = 0u;
    }
    *reinterpret_cast<uint2*>(g_agg16 + node * H + lane * 4) = o;
}

// ---------------------------------------------------------------------------
// mma compute core (fp16 m16n8k16): 8 warps (2x4), warp tile 64x32, BK=64.
// ---------------------------------------------------------------------------
__device__ __forceinline__ void mma_chunk16(const __half* As, const __half* Bs,
                                            float acc[4][4][4], int wm, int wn, int lane) {
    const int qr = lane >> 2, qk = lane & 3;
    #pragma unroll
    for (int ks = 0; ks < BK / 16; ks++) {
        uint32_t a[4][4], b[4][2];
        #pragma unroll
        for (int mt = 0; mt < 4; mt++) {
            const __half* p = As + (wm * 64 + mt * 16 + qr) * S_H + ks * 16 + qk * 2;
            a[mt][0] = *reinterpret_cast<const uint32_t*>(p);
            a[mt][1] = *reinterpret_cast<const uint32_t*>(p + 8 * S_H);
            a[mt][2] = *reinterpret_cast<const uint32_t*>(p + 8);
            a[mt][3] = *reinterpret_cast<const uint32_t*>(p + 8 * S_H + 8);
        }
        #pragma unroll
        for (int nt = 0; nt < 4; nt++) {
            const __half* p = Bs + (wn * 32 + nt * 8 + qr) * S_H + ks * 16 + qk * 2;
            b[nt][0] = *reinterpret_cast<const uint32_t*>(p);
            b[nt][1] = *reinterpret_cast<const uint32_t*>(p + 8);
        }
        #pragma unroll
        for (int mt = 0; mt < 4; mt++)
            #pragma unroll
            for (int nt = 0; nt < 4; nt++)
                mma_f16(acc[mt][nt], a[mt], b[nt]);
    }
}

// ---------------------------------------------------------------------------
// GEMM1 (fp16 mma): tile t=blockIdx.y of z @ Wcat.
// t=0 -> A (fp16 slab), t=1 -> T (+b_msg), t=2 -> C
// ---------------------------------------------------------------------------
__global__ void __launch_bounds__(256, 2)
gemm1_mma(const float* __restrict__ z, const float* __restrict__ bmsg, int M) {
    extern __shared__ __half smh[];
    __half* As = smh;
    __half* Bs = smh + TILE_H;
    const int tid = threadIdx.x, wid = tid >> 5, lane = tid & 31;
    const int wm = wid >> 2, wn = wid & 3;
    const int bm = blockIdx.x * 128;
    const int t  = blockIdx.y;
    const int bn = t * 128;
    const int lrow = tid >> 1, lhalf = tid & 1;
    float acc[4][4][4] = {};

    for (int c = 0; c < 2; c++) {
        int k0 = c * BK;
        #pragma unroll
        for (int i = 0; i < 8; i++) {
            int col = lhalf * 4 + i * 8;
            float4 av = make_float4(0.f, 0.f, 0.f, 0.f);
            if (bm + lrow < M)
                av = *reinterpret_cast<const float4*>(z + (bm + lrow) * H + k0 + col);
            uint2 ah; ah.x = pack_h2(av.x, av.y); ah.y = pack_h2(av.z, av.w);
            *reinterpret_cast<uint2*>(As + lrow * S_H + col) = ah;
            uint2 bh = *reinterpret_cast<const uint2*>(g_Bt + (bn + lrow) * H + k0 + col);
            *reinterpret_cast<uint2*>(Bs + lrow * S_H + col) = bh;
        }
        __syncthreads();
        mma_chunk16(As, Bs, acc, wm, wn, lane);
        __syncthreads();
    }

    const int qr = lane >> 2, qk = lane & 3;
    #pragma unroll
    for (int mt = 0; mt < 4; mt++) {
        #pragma unroll
        for (int nt = 0; nt < 4; nt++) {
            int lc = wn * 32 + nt * 8 + qk * 2;      // local col within 128-tile
            int r0 = bm + wm * 64 + mt * 16 + qr;
            int r1 = r0 + 8;
            if (t == 0) {
                if (r0 < M)
                    *reinterpret_cast<uint32_t*>(g_A16 + r0 * H + lc) =
                        pack_h2(acc[mt][nt][0], acc[mt][nt][1]);
                if (r1 < M)
                    *reinterpret_cast<uint32_t*>(g_A16 + r1 * H + lc) =
                        pack_h2(acc[mt][nt][2], acc[mt][nt][3]);
            } else {
                float bx = 0.f, by = 0.f;
                int off = (t == 1) ? lc : (128 + lc);
                if (t == 1) { bx = bmsg[lc]; by = bmsg[lc + 1]; }
                if (r0 < M) {
                    float2 v = make_float2(acc[mt][nt][0] + bx, acc[mt][nt][1] + by);
                    *reinterpret_cast<float2*>(g_P + r0 * PC + off) = v;
                }
                if (r1 < M) {
                    float2 v = make_float2(acc[mt][nt][2] + bx, acc[mt][nt][3] + by);
                    *reinterpret_cast<float2*>(g_P + r1 * PC + off) = v;
                }
            }
        }
    }
}

// ---------------------------------------------------------------------------
// GEMM2 (fp16 mma): out = agg @ Wu2 + C + b_upd; A = g_agg16 (pure copy).
// ---------------------------------------------------------------------------
__global__ void __launch_bounds__(256, 2)
gemm2_mma(const float* __restrict__ bupd, float* __restrict__ out, int M) {
    extern __shared__ __half smh[];
    __half* As = smh;
    __half* Bs = smh + TILE_H;
    const int tid = threadIdx.x, wid = tid >> 5, lane = tid & 31;
    const int wm = wid >> 2, wn = wid & 3;
    const int bm = blockIdx.x * 128;
    const int lrow = tid >> 1, lhalf = tid & 1;
    float acc[4][4][4] = {};

    for (int c = 0; c < 2; c++) {
        int k0 = c * BK;
        #pragma unroll
        for (int i = 0; i < 8; i++) {
            int col = lhalf * 4 + i * 8;
            uint2 ah = make_uint2(0u, 0u);
            if (bm + lrow < M)
                ah = *reinterpret_cast<const uint2*>(g_agg16 + (bm + lrow) * H + k0 + col);
            *reinterpret_cast<uint2*>(As + lrow * S_H + col) = ah;
            uint2 bh = *reinterpret_cast<const uint2*>(g_Bu + lrow * H + k0 + col);
            *reinterpret_cast<uint2*>(Bs + lrow * S_H + col) = bh;
        }
        __syncthreads();
        mma_chunk16(As, Bs, acc, wm, wn, lane);
        __syncthreads();
    }

    const int qr = lane >> 2, qk = lane & 3;
    #pragma unroll
    for (int mt = 0; mt < 4; mt++) {
        #pragma unroll
        for (int nt = 0; nt < 4; nt++) {
            int col = wn * 32 + nt * 8 + qk * 2;
            float bx = bupd[col], by = bupd[col + 1];
            int r0 = bm + wm * 64 + mt * 16 + qr;
            if (r0 < M) {
                float2 c2 = *reinterpret_cast<const float2*>(g_P + r0 * PC + 128 + col);
                float2 v = make_float2(acc[mt][nt][0] + c2.x + bx,
                                       acc[mt][nt][1] + c2.y + by);
                *reinterpret_cast<float2*>(out + r0 * H + col) = v;
            }
            int r1 = r0 + 8;
            if (r1 < M) {
                float2 c2 = *reinterpret_cast<const float2*>(g_P + r1 * PC + 128 + col);
                float2 v = make_float2(acc[mt][nt][2] + c2.x + bx,
                                       acc[mt][nt][3] + c2.y + by);
                *reinterpret_cast<float2*>(out + r1 * H + col) = v;
            }
        }
    }
}

// ---------------------------------------------------------------------------
extern "C" void kernel_launch(void* const* d_in, const int* in_sizes, int n_in,
                              void* d_out, int out_size) {
    const float* z    = (const float*)d_in[0];
    const int*   src  = (const int*)  d_in[1];
    const int*   dst  = (const int*)  d_in[2];
    const float* w    = (const float*)d_in[3];
    const float* Wmsg = (const float*)d_in[4];
    const float* bmsg = (const float*)d_in[5];
    const float* Wupd = (const float*)d_in[6];
    const float* bupd = (const float*)d_in[7];
    float* out = (float*)d_out;

    int n = in_sizes[0] / H;     // 50000
    int E = in_sizes[1];         // 640000

    static cudaStream_t s2 = nullptr;
    static cudaEvent_t evStart = nullptr, evCsr = nullptr;
    static bool init_done = false;
    if (!init_done) {            // first call is the uncaptured correctness run
        cudaFuncSetAttribute(gemm1_mma, cudaFuncAttributeMaxDynamicSharedMemorySize, SMEM_BYTES);
        cudaFuncSetAttribute(gemm2_mma, cudaFuncAttributeMaxDynamicSharedMemorySize, SMEM_BYTES);
        cudaStreamCreateWithFlags(&s2, cudaStreamNonBlocking);
        cudaEventCreateWithFlags(&evStart, cudaEventDisableTiming);
        cudaEventCreateWithFlags(&evCsr, cudaEventDisableTiming);
        init_done = true;
    }

    int nb_scan = (n + 511) / 512;
    int nbk = (n + 127) / 128;

    // fork: CSR build on s2, weights+GEMM1 on main stream
    cudaEventRecord(evStart, 0);
    cudaStreamWaitEvent(s2, evStart, 0);

    zero_cnt_kernel<<<(n + 255) / 256, 256, 0, s2>>>(n);
    hist_kernel<<<(E + 255) / 256, 256, 0, s2>>>(dst, E);
    scan1_kernel<<<nb_scan, 512, 0, s2>>>(n);
    scan2_kernel<<<1, 128, 0, s2>>>(nb_scan);
    scan3_kernel<<<(n + 255) / 256, 256, 0, s2>>>(n);
    scatter_kernel<<<(E + 255) / 256, 256, 0, s2>>>(src, dst, w, E);
    cudaEventRecord(evCsr, s2);

    pack_kernel<<<256, 256>>>(Wmsg, Wupd);
    gemm1_mma<<<dim3(nbk, 3), 256, SMEM_BYTES>>>(z, bmsg, n);

    // join: aggregate needs both gemm1 (A16, T) and scatter (CSR)
    cudaStreamWaitEvent(0, evCsr, 0);
    aggregate_kernel<<<(n * 32 + 255) / 256, 256>>>(n);
    gemm2_mma<<<nbk, 256, SMEM_BYTES>>>(bupd, out, n);
}

// round 17
// speedup vs baseline: 1.3032x; 1.0150x over previous
#include <cuda_runtime.h>
#include <cuda_fp16.h>
#include <cstdint>

#define H     128
#define MAXN  50000
#define MAXE  640000
#define PC    256                // g_P columns: [T | C]

#define BK      64
#define S_H     72               // smem row stride (halves); row stride 144B = 4 banks mod 32
#define TILE_H  (128 * S_H)      // halves per smem tile
#define SMEM_BYTES (2 * TILE_H * 2)

// ---- scratch (static device memory) ----
__device__ __align__(16) __half g_Bt[384 * H];    // GEMM1 B^T: [n][k] half
__device__ __align__(16) __half g_Bu[H * H];      // GEMM2 B^T: Wu2^T [n][k] half
__device__ __align__(16) float  g_v[H];           // W_msg weight column
__device__ __align__(16) __half g_A16[MAXN * H];  // fp16 A slab (12.8 MB, L2-resident)
__device__ __align__(16) float  g_P[MAXN * PC];   // per-node [T | C] fp32
__device__ __align__(16) __half g_agg16[MAXN * H];// aggregated (max + T, or 0) fp16
// CSR build
__device__ int   g_cnt[MAXN];
__device__ int   g_ro[MAXN];
__device__ int   g_cur[MAXN];
__device__ int   g_bsum[128];
__device__ int   g_boff[128];
__device__ __align__(8) int2 g_esw[MAXE];         // packed (src, weight-bits)

__device__ __forceinline__ void mma_f16(float* acc, const uint32_t* a, const uint32_t* b) {
    asm volatile(
        "mma.sync.aligned.m16n8k16.row.col.f32.f16.f16.f32 "
        "{%0,%1,%2,%3}, {%4,%5,%6,%7}, {%8,%9}, {%0,%1,%2,%3};"
        : "+f"(acc[0]), "+f"(acc[1]), "+f"(acc[2]), "+f"(acc[3])
        : "r"(a[0]), "r"(a[1]), "r"(a[2]), "r"(a[3]), "r"(b[0]), "r"(b[1]));
}
__device__ __forceinline__ void ldsm_x4(uint32_t* r, uint32_t addr) {
    asm volatile("ldmatrix.sync.aligned.m8n8.x4.shared.b16 {%0,%1,%2,%3}, [%4];"
        : "=r"(r[0]), "=r"(r[1]), "=r"(r[2]), "=r"(r[3]) : "r"(addr));
}
__device__ __forceinline__ uint32_t pack_h2(float x, float y) {
    __half2 h = __floats2half2_rn(x, y);
    return *reinterpret_cast<uint32_t*>(&h);
}

// ---------------------------------------------------------------------------
// Pack weights into half (transposed for col-major B frags).
// ---------------------------------------------------------------------------
__global__ void pack_kernel(const float* __restrict__ Wmsg,
                            const float* __restrict__ Wupd) {
    int idx = blockIdx.x * blockDim.x + threadIdx.x;
    if (idx < H) g_v[idx] = Wmsg[256 * H + idx];
    if (idx < 384 * H) {
        int n = idx / H, k = idx % H;
        float val;
        if (n < H)            val = Wmsg[k * H + n];
        else if (n < 2 * H)   val = Wmsg[(H + k) * H + (n - H)];
        else                  val = Wupd[k * H + (n - 2 * H)];
        g_Bt[idx] = __float2half_rn(val);
    } else if (idx < 384 * H + H * H) {
        int j = idx - 384 * H;
        int n = j / H, k = j % H;
        g_Bu[j] = __float2half_rn(Wupd[(H + k) * H + n]);
    }
}

// ---------------------------------------------------------------------------
// CSR build: zero -> histogram -> scan(3 stages) -> scatter
// ---------------------------------------------------------------------------
__global__ void zero_cnt_kernel(int n) {
    int i = blockIdx.x * blockDim.x + threadIdx.x;
    if (i < n) g_cnt[i] = 0;
}

__global__ void hist_kernel(const int* __restrict__ dst, int E) {
    int i = blockIdx.x * blockDim.x + threadIdx.x;
    if (i < E) atomicAdd(&g_cnt[dst[i]], 1);
}

__global__ void scan1_kernel(int n) {
    __shared__ int s[512];
    int t = threadIdx.x;
    int i = blockIdx.x * 512 + t;
    int v = (i < n) ? g_cnt[i] : 0;
    s[t] = v;
    __syncthreads();
    #pragma unroll
    for (int off = 1; off < 512; off <<= 1) {
        int u = (t >= off) ? s[t - off] : 0;
        __syncthreads();
        s[t] += u;
        __syncthreads();
    }
    if (i < n) g_ro[i] = s[t] - v;            // exclusive within block
    if (t == 511) g_bsum[blockIdx.x] = s[511];
}

__global__ void scan2_kernel(int nb) {
    __shared__ int s[128];
    int t = threadIdx.x;
    int v = (t < nb) ? g_bsum[t] : 0;
    s[t] = v;
    __syncthreads();
    #pragma unroll
    for (int off = 1; off < 128; off <<= 1) {
        int u = (t >= off) ? s[t - off] : 0;
        __syncthreads();
        s[t] += u;
        __syncthreads();
    }
    if (t < nb) g_boff[t] = s[t] - v;         // exclusive block offsets
}

__global__ void scan3_kernel(int n) {
    int i = blockIdx.x * blockDim.x + threadIdx.x;
    if (i < n) {
        int v = g_ro[i] + g_boff[i >> 9];
        g_ro[i] = v;
        g_cur[i] = v;
    }
}

__global__ void scatter_kernel(const int* __restrict__ src,
                               const int* __restrict__ dst,
                               const float* __restrict__ w, int E) {
    int i = blockIdx.x * blockDim.x + threadIdx.x;
    if (i < E) {
        int d = dst[i];
        int p = atomicAdd(&g_cur[d], 1);
        g_esw[p] = make_int2(src[i], __float_as_int(w[i]));
    }
}

// ---------------------------------------------------------------------------
// Aggregate: one warp per node; 8-edge batches; packed (src,w) stream.
// Math fp32; writes fp16 agg. Max is exact/associative -> deterministic.
// ---------------------------------------------------------------------------
__global__ void __launch_bounds__(256)
aggregate_kernel(int n) {
    int node = (blockIdx.x * blockDim.x + threadIdx.x) >> 5;
    int lane = threadIdx.x & 31;
    if (node >= n) return;
    int start = g_ro[node];
    int deg   = g_cnt[node];

    float4 vv = *reinterpret_cast<const float4*>(g_v + lane * 4);
    const float NEGINF = __int_as_float(0xff800000);
    float4 m = make_float4(NEGINF, NEGINF, NEGINF, NEGINF);

    for (int e = 0; e < deg; e += 8) {
        int nb = deg - e; if (nb > 8) nb = 8;
        int2 sw8[8];
        #pragma unroll
        for (int j = 0; j < 8; j++) {
            int idx = start + e + ((j < nb) ? j : 0);
            sw8[j] = __ldg(g_esw + idx);
        }
        uint2 a8[8];
        #pragma unroll
        for (int j = 0; j < 8; j++)
            a8[j] = __ldg(reinterpret_cast<const uint2*>(g_A16 + sw8[j].x * H) + lane);
        #pragma unroll
        for (int j = 0; j < 8; j++) {
            if (j < nb) {
                float wt = __int_as_float(sw8[j].y);
                __half2 h0 = *reinterpret_cast<__half2*>(&a8[j].x);
                __half2 h1 = *reinterpret_cast<__half2*>(&a8[j].y);
                float2 f0 = __half22float2(h0);
                float2 f1 = __half22float2(h1);
                m.x = fmaxf(m.x, fmaf(wt, vv.x, f0.x));
                m.y = fmaxf(m.y, fmaf(wt, vv.y, f0.y));
                m.z = fmaxf(m.z, fmaf(wt, vv.z, f1.x));
                m.w = fmaxf(m.w, fmaf(wt, vv.w, f1.y));
            }
        }
    }

    uint2 o;
    if (deg > 0) {
        float4 t4 = *reinterpret_cast<const float4*>(g_P + node * PC + lane * 4);
        o.x = pack_h2(m.x + t4.x, m.y + t4.y);
        o.y = pack_h2(m.z + t4.z, m.w + t4.w);
    } else {
        o.x = 0u; o.y = 0u;
    }
    *reinterpret_cast<uint2*>(g_agg16 + node * H + lane * 4) = o;
}

// ---------------------------------------------------------------------------
// mma compute core (fp16 m16n8k16 + ldmatrix): 8 warps (2x4), warp tile
// 64x32, BK=64. 6 LDSM per k-step instead of 24 scalar LDS.
// ---------------------------------------------------------------------------
__device__ __forceinline__ void mma_chunk16(uint32_t As_u, uint32_t Bs_u,
                                            float acc[4][4][4], int wm, int wn, int lane) {
    // A addressing: lanes 0-15 -> rows 0-15 @k0 ; lanes 16-31 -> rows 0-15 @k8
    const uint32_t a_row  = lane & 15;
    const uint32_t a_koff = (lane >> 4) * 8;
    // B addressing (per nt-pair x4): grp = lane>>3 -> {nt0@k0, nt0@k8, nt1@k0, nt1@k8}
    const int grp = lane >> 3, rin = lane & 7;
    const uint32_t b_n_off = (uint32_t)((grp >> 1) * 8 + rin);
    const uint32_t b_koff  = (uint32_t)((grp & 1) * 8);

    #pragma unroll
    for (int ks = 0; ks < BK / 16; ks++) {
        uint32_t a[4][4], b[4][2];
        #pragma unroll
        for (int mt = 0; mt < 4; mt++) {
            uint32_t addr = As_u +
                (((wm * 64 + mt * 16 + a_row) * S_H) + (uint32_t)(ks * 16) + a_koff) * 2;
            ldsm_x4(a[mt], addr);
        }
        #pragma unroll
        for (int p = 0; p < 2; p++) {
            uint32_t bp[4];
            uint32_t addr = Bs_u +
                (((wn * 32 + p * 16 + b_n_off) * S_H) + (uint32_t)(ks * 16) + b_koff) * 2;
            ldsm_x4(bp, addr);
            b[2 * p][0] = bp[0]; b[2 * p][1] = bp[1];
            b[2 * p + 1][0] = bp[2]; b[2 * p + 1][1] = bp[3];
        }
        #pragma unroll
        for (int mt = 0; mt < 4; mt++)
            #pragma unroll
            for (int nt = 0; nt < 4; nt++)
                mma_f16(acc[mt][nt], a[mt], b[nt]);
    }
}

// ---------------------------------------------------------------------------
// GEMM1 (fp16 mma): tile t=blockIdx.y of z @ Wcat.
// t=0 -> A (fp16 slab), t=1 -> T (+b_msg), t=2 -> C
// ---------------------------------------------------------------------------
__global__ void __launch_bounds__(256, 2)
gemm1_mma(const float* __restrict__ z, const float* __restrict__ bmsg, int M) {
    extern __shared__ __half smh[];
    __half* As = smh;
    __half* Bs = smh + TILE_H;
    const uint32_t As_u = (uint32_t)__cvta_generic_to_shared(As);
    const uint32_t Bs_u = (uint32_t)__cvta_generic_to_shared(Bs);
    const int tid = threadIdx.x, wid = tid >> 5, lane = tid & 31;
    const int wm = wid >> 2, wn = wid & 3;
    const int bm = blockIdx.x * 128;
    const int t  = blockIdx.y;
    const int bn = t * 128;
    const int lrow = tid >> 1, lhalf = tid & 1;
    float acc[4][4][4] = {};

    for (int c = 0; c < 2; c++) {
        int k0 = c * BK;
        #pragma unroll
        for (int i = 0; i < 8; i++) {
            int col = lhalf * 4 + i * 8;
            float4 av = make_float4(0.f, 0.f, 0.f, 0.f);
            if (bm + lrow < M)
                av = *reinterpret_cast<const float4*>(z + (bm + lrow) * H + k0 + col);
            uint2 ah; ah.x = pack_h2(av.x, av.y); ah.y = pack_h2(av.z, av.w);
            *reinterpret_cast<uint2*>(As + lrow * S_H + col) = ah;
            uint2 bh = *reinterpret_cast<const uint2*>(g_Bt + (bn + lrow) * H + k0 + col);
            *reinterpret_cast<uint2*>(Bs + lrow * S_H + col) = bh;
        }
        __syncthreads();
        mma_chunk16(As_u, Bs_u, acc, wm, wn, lane);
        __syncthreads();
    }

    const int qr = lane >> 2, qk = lane & 3;
    #pragma unroll
    for (int mt = 0; mt < 4; mt++) {
        #pragma unroll
        for (int nt = 0; nt < 4; nt++) {
            int lc = wn * 32 + nt * 8 + qk * 2;      // local col within 128-tile
            int r0 = bm + wm * 64 + mt * 16 + qr;
            int r1 = r0 + 8;
            if (t == 0) {
                if (r0 < M)
                    *reinterpret_cast<uint32_t*>(g_A16 + r0 * H + lc) =
                        pack_h2(acc[mt][nt][0], acc[mt][nt][1]);
                if (r1 < M)
                    *reinterpret_cast<uint32_t*>(g_A16 + r1 * H + lc) =
                        pack_h2(acc[mt][nt][2], acc[mt][nt][3]);
            } else {
                float bx = 0.f, by = 0.f;
                int off = (t == 1) ? lc : (128 + lc);
                if (t == 1) { bx = bmsg[lc]; by = bmsg[lc + 1]; }
                if (r0 < M) {
                    float2 v = make_float2(acc[mt][nt][0] + bx, acc[mt][nt][1] + by);
                    *reinterpret_cast<float2*>(g_P + r0 * PC + off) = v;
                }
                if (r1 < M) {
                    float2 v = make_float2(acc[mt][nt][2] + bx, acc[mt][nt][3] + by);
                    *reinterpret_cast<float2*>(g_P + r1 * PC + off) = v;
                }
            }
        }
    }
}

// ---------------------------------------------------------------------------
// GEMM2 (fp16 mma): out = agg @ Wu2 + C + b_upd; A = g_agg16 (pure copy).
// ---------------------------------------------------------------------------
__global__ void __launch_bounds__(256, 2)
gemm2_mma(const float* __restrict__ bupd, float* __restrict__ out, int M) {
    extern __shared__ __half smh[];
    __half* As = smh;
    __half* Bs = smh + TILE_H;
    const uint32_t As_u = (uint32_t)__cvta_generic_to_shared(As);
    const uint32_t Bs_u = (uint32_t)__cvta_generic_to_shared(Bs);
    const int tid = threadIdx.x, wid = tid >> 5, lane = tid & 31;
    const int wm = wid >> 2, wn = wid & 3;
    const int bm = blockIdx.x * 128;
    const int lrow = tid >> 1, lhalf = tid & 1;
    float acc[4][4][4] = {};

    for (int c = 0; c < 2; c++) {
        int k0 = c * BK;
        #pragma unroll
        for (int i = 0; i < 8; i++) {
            int col = lhalf * 4 + i * 8;
            uint2 ah = make_uint2(0u, 0u);
            if (bm + lrow < M)
                ah = *reinterpret_cast<const uint2*>(g_agg16 + (bm + lrow) * H + k0 + col);
            *reinterpret_cast<uint2*>(As + lrow * S_H + col) = ah;
            uint2 bh = *reinterpret_cast<const uint2*>(g_Bu + lrow * H + k0 + col);
            *reinterpret_cast<uint2*>(Bs + lrow * S_H + col) = bh;
        }
        __syncthreads();
        mma_chunk16(As_u, Bs_u, acc, wm, wn, lane);
        __syncthreads();
    }

    const int qr = lane >> 2, qk = lane & 3;
    #pragma unroll
    for (int mt = 0; mt < 4; mt++) {
        #pragma unroll
        for (int nt = 0; nt < 4; nt++) {
            int col = wn * 32 + nt * 8 + qk * 2;
            float bx = bupd[col], by = bupd[col + 1];
            int r0 = bm + wm * 64 + mt * 16 + qr;
            if (r0 < M) {
                float2 c2 = *reinterpret_cast<const float2*>(g_P + r0 * PC + 128 + col);
                float2 v = make_float2(acc[mt][nt][0] + c2.x + bx,
                                       acc[mt][nt][1] + c2.y + by);
                *reinterpret_cast<float2*>(out + r0 * H + col) = v;
            }
            int r1 = r0 + 8;
            if (r1 < M) {
                float2 c2 = *reinterpret_cast<const float2*>(g_P + r1 * PC + 128 + col);
                float2 v = make_float2(acc[mt][nt][2] + c2.x + bx,
                                       acc[mt][nt][3] + c2.y + by);
                *reinterpret_cast<float2*>(out + r1 * H + col) = v;
            }
        }
    }
}

// ---------------------------------------------------------------------------
extern "C" void kernel_launch(void* const* d_in, const int* in_sizes, int n_in,
                              void* d_out, int out_size) {
    const float* z    = (const float*)d_in[0];
    const int*   src  = (const int*)  d_in[1];
    const int*   dst  = (const int*)  d_in[2];
    const float* w    = (const float*)d_in[3];
    const float* Wmsg = (const float*)d_in[4];
    const float* bmsg = (const float*)d_in[5];
    const float* Wupd = (const float*)d_in[6];
    const float* bupd = (const float*)d_in[7];
    float* out = (float*)d_out;

    int n = in_sizes[0] / H;     // 50000
    int E = in_sizes[1];         // 640000

    static cudaStream_t s2 = nullptr;
    static cudaEvent_t evStart = nullptr, evCsr = nullptr;
    static bool init_done = false;
    if (!init_done) {            // first call is the uncaptured correctness run
        cudaFuncSetAttribute(gemm1_mma, cudaFuncAttributeMaxDynamicSharedMemorySize, SMEM_BYTES);
        cudaFuncSetAttribute(gemm2_mma, cudaFuncAttributeMaxDynamicSharedMemorySize, SMEM_BYTES);
        cudaStreamCreateWithFlags(&s2, cudaStreamNonBlocking);
        cudaEventCreateWithFlags(&evStart, cudaEventDisableTiming);
        cudaEventCreateWithFlags(&evCsr, cudaEventDisableTiming);
        init_done = true;
    }

    int nb_scan = (n + 511) / 512;
    int nbk = (n + 127) / 128;

    // fork: CSR build on s2, weights+GEMM1 on main stream
    cudaEventRecord(evStart, 0);
    cudaStreamWaitEvent(s2, evStart, 0);

    zero_cnt_kernel<<<(n + 255) / 256, 256, 0, s2>>>(n);
    hist_kernel<<<(E + 255) / 256, 256, 0, s2>>>(dst, E);
    scan1_kernel<<<nb_scan, 512, 0, s2>>>(n);
    scan2_kernel<<<1, 128, 0, s2>>>(nb_scan);
    scan3_kernel<<<(n + 255) / 256, 256, 0, s2>>>(n);
    scatter_kernel<<<(E + 255) / 256, 256, 0, s2>>>(src, dst, w, E);
    cudaEventRecord(evCsr, s2);

    pack_kernel<<<256, 256>>>(Wmsg, Wupd);
    gemm1_mma<<<dim3(nbk, 3), 256, SMEM_BYTES>>>(z, bmsg, n);

    // join: aggregate needs both gemm1 (A16, T) and scatter (CSR)
    cudaStreamWaitEvent(0, evCsr, 0);
    aggregate_kernel<<<(n * 32 + 255) / 256, 256>>>(n);
    gemm2_mma<<<nbk, 256, SMEM_BYTES>>>(bupd, out, n);
}